// round 10
// baseline (speedup 1.0000x reference)
#include <cuda_runtime.h>
#include <cuda_bf16.h>
#include <cstdint>

#define B_ROWS 8192
#define DIM    128
#define BM     128
#define SH     136            // halves per smem bf16 row (272 B): LDSM conflict-free
#define NBLK   64
#define NTILES 2080           // 64 diag + 2016 off-diag
#define NEG_INF_F (-1e30f)
#define POS_INF_F ( 1e30f)
#define MARGIN_F  0.2f

// ---------------- device-global state ----------------
__device__ unsigned       g_max_enc[B_ROWS];
__device__ unsigned       g_min_enc[B_ROWS];
__device__ __nv_bfloat16  g_im_bf16[B_ROWS * DIM];   // 2 MB, L2-resident
__device__ int            g_ids32[B_ROWS];
__device__ int            g_done;                    // completed-CTA counter (self-resetting)

__device__ __forceinline__ unsigned enc_f(float f) {
    unsigned u = __float_as_uint(f);
    return (u & 0x80000000u) ? ~u : (u | 0x80000000u);
}
__device__ __forceinline__ float dec_f(unsigned u) {
    return __uint_as_float((u & 0x80000000u) ? (u & 0x7FFFFFFFu) : ~u);
}
__device__ __forceinline__ uint32_t smem_u32(const void* p) {
    uint32_t a;
    asm("{ .reg .u64 t; cvta.to.shared.u64 t, %1; cvt.u32.u64 %0, t; }" : "=r"(a) : "l"(p));
    return a;
}
#define LDSM_X4(r0, r1, r2, r3, addr) \
    asm volatile("ldmatrix.sync.aligned.m8n8.x4.shared.b16 {%0,%1,%2,%3}, [%4];" \
                 : "=r"(r0), "=r"(r1), "=r"(r2), "=r"(r3) : "r"(addr))

// ---------------------------------------------------------------------------
// Kernel 1: convert im -> bf16 (MLP=4), ids -> int32, clear reductions.
// 65536 threads; each issues 4 INDEPENDENT LDG.128s (stride 65536 float4).
// ids dtype: SAFE detection from odd words 1..129 (in bounds either dtype).
// ---------------------------------------------------------------------------
__global__ void convert_kernel(const float* __restrict__ im, const void* __restrict__ ids) {
    __shared__ int s_is64;
    const int tid = blockIdx.x * blockDim.x + threadIdx.x;   // 256*256 = 65536

    if (blockIdx.x < 32) {
        if (threadIdx.x < 32) {
            const unsigned* w = (const unsigned*)ids;
            unsigned v = w[2 * threadIdx.x + 1] | w[2 * threadIdx.x + 65];
            unsigned any = __ballot_sync(0xffffffffu, v != 0u);
            if (threadIdx.x == 0) s_is64 = (any == 0u) ? 1 : 0;
        }
        __syncthreads();
        g_max_enc[tid] = enc_f(NEG_INF_F);
        g_min_enc[tid] = enc_f(POS_INF_F);
        g_ids32[tid] = s_is64 ? (int)((const long long*)ids)[tid]
                              : ((const int*)ids)[tid];
    }
    const float4* in4 = (const float4*)im;
    float4 v0 = in4[tid];                // 4 independent loads in flight
    float4 v1 = in4[tid + 65536];
    float4 v2 = in4[tid + 131072];
    float4 v3 = in4[tid + 196608];
    __nv_bfloat162* o = (__nv_bfloat162*)g_im_bf16;
    o[2 * tid + 0]            = __floats2bfloat162_rn(v0.x, v0.y);
    o[2 * tid + 1]            = __floats2bfloat162_rn(v0.z, v0.w);
    o[2 * (tid + 65536) + 0]  = __floats2bfloat162_rn(v1.x, v1.y);
    o[2 * (tid + 65536) + 1]  = __floats2bfloat162_rn(v1.z, v1.w);
    o[2 * (tid + 131072) + 0] = __floats2bfloat162_rn(v2.x, v2.y);
    o[2 * (tid + 131072) + 1] = __floats2bfloat162_rn(v2.z, v2.w);
    o[2 * (tid + 196608) + 0] = __floats2bfloat162_rn(v3.x, v3.y);
    o[2 * (tid + 196608) + 1] = __floats2bfloat162_rn(v3.z, v3.w);
}

// ---------------------------------------------------------------------------
// Kernel 2: symmetric bf16 mma.sync tile, register-pooled masked reduction
// (identical mainloop/epilogue to R9), plus fused last-CTA finalize.
// ---------------------------------------------------------------------------
#define SROW_OFF (2 * BM * SH * 2)                 // 69632
#define SCOL_OFF (SROW_OFF + 8 * BM * 8)           // + 8KB
#define SMEM_TOTAL (SCOL_OFF + 32 * BM * 8)        // + 32KB = 110592

__global__ void __launch_bounds__(256, 2)
tile_kernel(float* __restrict__ out) {
    // ---- block-id -> (bi, bj): first 64 = diagonal, rest strict-upper ----
    int bi, bj;
    {
        const int bid = blockIdx.x;
        if (bid < NBLK) { bi = bid; bj = bid; }
        else {
            int k = bid - NBLK;
            int b = (int)(63.5f - sqrtf(4032.25f - 2.0f * (float)k));
            if (b < 0) b = 0;
            while (63 * b - b * (b - 1) / 2 > k) --b;
            while (63 * (b + 1) - (b + 1) * b / 2 <= k) ++b;
            bi = b;
            bj = b + 1 + (k - (63 * b - b * (b - 1) / 2));
        }
    }
    const bool diag = (bi == bj);
    const int m0 = bi * BM, n0 = bj * BM;

    extern __shared__ char smem[];
    unsigned short* As = (unsigned short*)smem;          // [BM][SH]
    unsigned short* Bs = As + BM * SH;                   // [BM][SH]
    float2* sRow = (float2*)(smem + SROW_OFF);           // [8][BM]
    float2* sCol = (float2*)(smem + SCOL_OFF);           // [32][BM]
    __shared__ int s_idr[BM], s_idc[BM];
    __shared__ bool s_last;

    const int tid = threadIdx.x;
    if (tid < BM) {
        s_idr[tid] = g_ids32[m0 + tid];
        s_idc[tid] = g_ids32[n0 + tid];
    }

    // Stage bf16 tiles: 2048 x 16B each.
#pragma unroll
    for (int it = 0; it < 8; ++it) {
        int idx = it * 256 + tid;
        int row = idx >> 4, q = idx & 15;
        *(uint4*)(As + row * SH + q * 8) =
            *(const uint4*)(g_im_bf16 + (size_t)(m0 + row) * DIM + q * 8);
        *(uint4*)(Bs + row * SH + q * 8) =
            *(const uint4*)(g_im_bf16 + (size_t)(n0 + row) * DIM + q * 8);
    }
    __syncthreads();

    const int warp = tid >> 5, lane = tid & 31;
    const int wm = warp >> 1, wn = warp & 1;     // warp tile origin (wm*32, wn*64)
    const int g = lane >> 2, tig = lane & 3;
    const int grp = lane >> 3, rin = lane & 7;

    const uint32_t As32 = smem_u32(As), Bs32 = smem_u32(Bs);
    uint32_t aaddr[2], baddr[4];
#pragma unroll
    for (int mt = 0; mt < 2; ++mt)
        aaddr[mt] = As32 + 2 * ((wm * 32 + mt * 16 + (grp & 1) * 8 + rin) * SH + (grp >> 1) * 8);
#pragma unroll
    for (int q = 0; q < 4; ++q)
        baddr[q] = Bs32 + 2 * ((wn * 64 + 16 * q + (grp >> 1) * 8 + rin) * SH + (grp & 1) * 8);

    float acc[2][8][4];
#pragma unroll
    for (int mt = 0; mt < 2; ++mt)
#pragma unroll
        for (int nt = 0; nt < 8; ++nt)
#pragma unroll
            for (int r = 0; r < 4; ++r) acc[mt][nt][r] = 0.0f;

#pragma unroll
    for (int ks = 0; ks < 8; ++ks) {
        const uint32_t koff = ks * 32;
        unsigned a[2][4], b[8][2];
#pragma unroll
        for (int mt = 0; mt < 2; ++mt)
            LDSM_X4(a[mt][0], a[mt][1], a[mt][2], a[mt][3], aaddr[mt] + koff);
#pragma unroll
        for (int q = 0; q < 4; ++q)
            LDSM_X4(b[2 * q][0], b[2 * q][1], b[2 * q + 1][0], b[2 * q + 1][1], baddr[q] + koff);
#pragma unroll
        for (int mt = 0; mt < 2; ++mt)
#pragma unroll
            for (int nt = 0; nt < 8; ++nt) {
                asm volatile(
                    "mma.sync.aligned.m16n8k16.row.col.f32.bf16.bf16.f32 "
                    "{%0,%1,%2,%3}, {%4,%5,%6,%7}, {%8,%9}, {%0,%1,%2,%3};"
                    : "+f"(acc[mt][nt][0]), "+f"(acc[mt][nt][1]),
                      "+f"(acc[mt][nt][2]), "+f"(acc[mt][nt][3])
                    : "r"(a[mt][0]), "r"(a[mt][1]), "r"(a[mt][2]), "r"(a[mt][3]),
                      "r"(b[nt][0]), "r"(b[nt][1]));
            }
    }
    // No barrier: partial arrays don't alias As/Bs.

    // ---- register-pooled epilogue (exact R9) ----
    int rids[4];
#pragma unroll
    for (int mt = 0; mt < 2; ++mt)
#pragma unroll
        for (int half = 0; half < 2; ++half)
            rids[mt * 2 + half] = s_idr[wm * 32 + mt * 16 + g + half * 8];

    float rmin[4] = {POS_INF_F, POS_INF_F, POS_INF_F, POS_INF_F};
    float rmax[4] = {NEG_INF_F, NEG_INF_F, NEG_INF_F, NEG_INF_F};

#pragma unroll
    for (int ph = 0; ph < 2; ++ph) {                 // two phases of 4 nt (8 cols)
        float cmin[8], cmax[8];
        int cids[8];
#pragma unroll
        for (int i = 0; i < 8; ++i) {
            cmin[i] = POS_INF_F; cmax[i] = NEG_INF_F;
            int nt = ph * 4 + (i >> 1);
            cids[i] = s_idc[wn * 64 + nt * 8 + 2 * tig + (i & 1)];
        }
#pragma unroll
        for (int i = 0; i < 8; ++i) {
            const int nt = ph * 4 + (i >> 1), e = i & 1;
            const int lc = wn * 64 + nt * 8 + 2 * tig + e;
            const int cid = cids[i];
#pragma unroll
            for (int mt = 0; mt < 2; ++mt)
#pragma unroll
                for (int half = 0; half < 2; ++half) {
                    const int ri = mt * 2 + half;
                    float s = acc[mt][nt][half * 2 + e];
                    if (diag && (wm * 32 + mt * 16 + g + half * 8) == lc) s = 0.0f;
                    if (rids[ri] == cid) {
                        rmin[ri] = fminf(rmin[ri], s);
                        cmin[i]  = fminf(cmin[i], s);
                    } else {
                        rmax[ri] = fmaxf(rmax[ri], s);
                        cmax[i]  = fmaxf(cmax[i], s);
                    }
                }
        }
        if (!diag) {
            const int slot = wm * 8 + g;             // 0..31
#pragma unroll
            for (int i = 0; i < 8; ++i) {
                const int nt = ph * 4 + (i >> 1);
                const int lc = wn * 64 + nt * 8 + 2 * tig + (i & 1);
                sCol[slot * BM + lc] = make_float2(cmin[i], cmax[i]);
            }
        }
    }
    {
        const int slot = wn * 4 + tig;               // 0..7
#pragma unroll
        for (int ri = 0; ri < 4; ++ri) {
            const int lr = wm * 32 + (ri >> 1) * 16 + g + (ri & 1) * 8;
            sRow[slot * BM + lr] = make_float2(rmin[ri], rmax[ri]);
        }
    }
    __syncthreads();

    if (tid < BM) {
        float vmin = POS_INF_F, vmax = NEG_INF_F;
#pragma unroll
        for (int s = 0; s < 8; ++s) {
            float2 p = sRow[s * BM + tid];
            vmin = fminf(vmin, p.x);
            vmax = fmaxf(vmax, p.y);
        }
        atomicMax(&g_max_enc[m0 + tid], enc_f(vmax));
        atomicMin(&g_min_enc[m0 + tid], enc_f(vmin));
    } else if (!diag) {
        const int c = tid - BM;
        float vmin = POS_INF_F, vmax = NEG_INF_F;
#pragma unroll
        for (int s = 0; s < 32; ++s) {
            float2 p = sCol[s * BM + c];
            vmin = fminf(vmin, p.x);
            vmax = fmaxf(vmax, p.y);
        }
        atomicMax(&g_max_enc[n0 + c], enc_f(vmax));
        atomicMin(&g_min_enc[n0 + c], enc_f(vmin));
    }

    // ---- fused finalize: last CTA reduces the loss and resets the counter ----
    __threadfence();
    __syncthreads();
    if (tid == 0) s_last = (atomicAdd(&g_done, 1) == NTILES - 1);
    __syncthreads();
    if (s_last) {
        __threadfence();
        float* part = (float*)sRow;                  // reuse partial buffer
        float s = 0.0f;
        for (int i = tid; i < B_ROWS; i += 256)
            s += fmaxf(MARGIN_F + dec_f(g_max_enc[i]) - dec_f(g_min_enc[i]), 0.0f);
        part[tid] = s;
        __syncthreads();
        for (int o = 128; o; o >>= 1) {
            if (tid < o) part[tid] += part[tid + o];
            __syncthreads();
        }
        if (tid == 0) {
            out[0] = part[0];
            g_done = 0;                              // reset for next graph replay
        }
    }
}

extern "C" void kernel_launch(void* const* d_in, const int* in_sizes, int n_in,
                              void* d_out, int out_size) {
    const float* im  = (const float*)d_in[0];
    const void*  ids = d_in[1];

    cudaFuncSetAttribute(tile_kernel, cudaFuncAttributeMaxDynamicSharedMemorySize, SMEM_TOTAL);

    convert_kernel<<<256, 256>>>(im, ids);
    tile_kernel<<<NTILES, 256, SMEM_TOTAL>>>((float*)d_out);
}

// round 11
// speedup vs baseline: 1.0413x; 1.0413x over previous
#include <cuda_runtime.h>
#include <cuda_bf16.h>
#include <cstdint>

#define B_ROWS 8192
#define DIM    128
#define BM     128
#define SH     136            // halves per smem bf16 row (272 B): LDSM conflict-free
#define NBLK   64
#define NTILES 2080           // 64 diag + 2016 off-diag
#define NEG_INF_F (-1e30f)
#define POS_INF_F ( 1e30f)
#define MARGIN_F  0.2f

// ---------------- device-global state ----------------
__device__ unsigned       g_max_enc[B_ROWS];
__device__ unsigned       g_min_enc[B_ROWS];
__device__ __nv_bfloat16  g_im_bf16[B_ROWS * DIM];   // 2 MB, L2-resident
__device__ int            g_ids32[B_ROWS];

__device__ __forceinline__ unsigned enc_f(float f) {
    unsigned u = __float_as_uint(f);
    return (u & 0x80000000u) ? ~u : (u | 0x80000000u);
}
__device__ __forceinline__ float dec_f(unsigned u) {
    return __uint_as_float((u & 0x80000000u) ? (u & 0x7FFFFFFFu) : ~u);
}
__device__ __forceinline__ uint32_t smem_u32(const void* p) {
    uint32_t a;
    asm("{ .reg .u64 t; cvta.to.shared.u64 t, %1; cvt.u32.u64 %0, t; }" : "=r"(a) : "l"(p));
    return a;
}
#define LDSM_X4(r0, r1, r2, r3, addr) \
    asm volatile("ldmatrix.sync.aligned.m8n8.x4.shared.b16 {%0,%1,%2,%3}, [%4];" \
                 : "=r"(r0), "=r"(r1), "=r"(r2), "=r"(r3) : "r"(addr))

// ---------------------------------------------------------------------------
// Kernel 1: convert im -> bf16 (MLP=4), ids -> int32, clear reductions.
// 65536 threads; each issues 4 INDEPENDENT LDG.128s (stride 65536 float4).
// ids dtype: SAFE detection from odd words 1..129 (in bounds either dtype).
// ---------------------------------------------------------------------------
__global__ void convert_kernel(const float* __restrict__ im, const void* __restrict__ ids) {
    __shared__ int s_is64;
    const int tid = blockIdx.x * blockDim.x + threadIdx.x;   // 256*256 = 65536

    if (blockIdx.x < 32) {
        if (threadIdx.x < 32) {
            const unsigned* w = (const unsigned*)ids;
            unsigned v = w[2 * threadIdx.x + 1] | w[2 * threadIdx.x + 65];
            unsigned any = __ballot_sync(0xffffffffu, v != 0u);
            if (threadIdx.x == 0) s_is64 = (any == 0u) ? 1 : 0;
        }
        __syncthreads();
        g_max_enc[tid] = enc_f(NEG_INF_F);
        g_min_enc[tid] = enc_f(POS_INF_F);
        g_ids32[tid] = s_is64 ? (int)((const long long*)ids)[tid]
                              : ((const int*)ids)[tid];
    }
    const float4* in4 = (const float4*)im;
    float4 v0 = in4[tid];                // 4 independent loads in flight
    float4 v1 = in4[tid + 65536];
    float4 v2 = in4[tid + 131072];
    float4 v3 = in4[tid + 196608];
    __nv_bfloat162* o = (__nv_bfloat162*)g_im_bf16;
    o[2 * tid + 0]            = __floats2bfloat162_rn(v0.x, v0.y);
    o[2 * tid + 1]            = __floats2bfloat162_rn(v0.z, v0.w);
    o[2 * (tid + 65536) + 0]  = __floats2bfloat162_rn(v1.x, v1.y);
    o[2 * (tid + 65536) + 1]  = __floats2bfloat162_rn(v1.z, v1.w);
    o[2 * (tid + 131072) + 0] = __floats2bfloat162_rn(v2.x, v2.y);
    o[2 * (tid + 131072) + 1] = __floats2bfloat162_rn(v2.z, v2.w);
    o[2 * (tid + 196608) + 0] = __floats2bfloat162_rn(v3.x, v3.y);
    o[2 * (tid + 196608) + 1] = __floats2bfloat162_rn(v3.z, v3.w);
}

// ---------------------------------------------------------------------------
// Kernel 2: symmetric bf16 mma.sync tile, register-pooled masked reduction.
// EXACT R9 kernel (49.7us proven): no threadfence, no done-counter.
// ---------------------------------------------------------------------------
#define SROW_OFF (2 * BM * SH * 2)                 // 69632
#define SCOL_OFF (SROW_OFF + 8 * BM * 8)           // + 8KB
#define SMEM_TOTAL (SCOL_OFF + 32 * BM * 8)        // + 32KB = 110592

__global__ void __launch_bounds__(256, 2)
tile_kernel(void) {
    // ---- block-id -> (bi, bj): first 64 = diagonal, rest strict-upper ----
    int bi, bj;
    {
        const int bid = blockIdx.x;
        if (bid < NBLK) { bi = bid; bj = bid; }
        else {
            int k = bid - NBLK;
            int b = (int)(63.5f - sqrtf(4032.25f - 2.0f * (float)k));
            if (b < 0) b = 0;
            while (63 * b - b * (b - 1) / 2 > k) --b;
            while (63 * (b + 1) - (b + 1) * b / 2 <= k) ++b;
            bi = b;
            bj = b + 1 + (k - (63 * b - b * (b - 1) / 2));
        }
    }
    const bool diag = (bi == bj);
    const int m0 = bi * BM, n0 = bj * BM;

    extern __shared__ char smem[];
    unsigned short* As = (unsigned short*)smem;          // [BM][SH]
    unsigned short* Bs = As + BM * SH;                   // [BM][SH]
    float2* sRow = (float2*)(smem + SROW_OFF);           // [8][BM]
    float2* sCol = (float2*)(smem + SCOL_OFF);           // [32][BM]
    __shared__ int s_idr[BM], s_idc[BM];

    const int tid = threadIdx.x;
    if (tid < BM) {
        s_idr[tid] = g_ids32[m0 + tid];
        s_idc[tid] = g_ids32[n0 + tid];
    }

    // Stage bf16 tiles: 2048 x 16B each.
#pragma unroll
    for (int it = 0; it < 8; ++it) {
        int idx = it * 256 + tid;
        int row = idx >> 4, q = idx & 15;
        *(uint4*)(As + row * SH + q * 8) =
            *(const uint4*)(g_im_bf16 + (size_t)(m0 + row) * DIM + q * 8);
        *(uint4*)(Bs + row * SH + q * 8) =
            *(const uint4*)(g_im_bf16 + (size_t)(n0 + row) * DIM + q * 8);
    }
    __syncthreads();

    const int warp = tid >> 5, lane = tid & 31;
    const int wm = warp >> 1, wn = warp & 1;     // warp tile origin (wm*32, wn*64)
    const int g = lane >> 2, tig = lane & 3;
    const int grp = lane >> 3, rin = lane & 7;

    const uint32_t As32 = smem_u32(As), Bs32 = smem_u32(Bs);
    uint32_t aaddr[2], baddr[4];
#pragma unroll
    for (int mt = 0; mt < 2; ++mt)
        aaddr[mt] = As32 + 2 * ((wm * 32 + mt * 16 + (grp & 1) * 8 + rin) * SH + (grp >> 1) * 8);
#pragma unroll
    for (int q = 0; q < 4; ++q)
        baddr[q] = Bs32 + 2 * ((wn * 64 + 16 * q + (grp >> 1) * 8 + rin) * SH + (grp & 1) * 8);

    float acc[2][8][4];
#pragma unroll
    for (int mt = 0; mt < 2; ++mt)
#pragma unroll
        for (int nt = 0; nt < 8; ++nt)
#pragma unroll
            for (int r = 0; r < 4; ++r) acc[mt][nt][r] = 0.0f;

#pragma unroll
    for (int ks = 0; ks < 8; ++ks) {
        const uint32_t koff = ks * 32;
        unsigned a[2][4], b[8][2];
#pragma unroll
        for (int mt = 0; mt < 2; ++mt)
            LDSM_X4(a[mt][0], a[mt][1], a[mt][2], a[mt][3], aaddr[mt] + koff);
#pragma unroll
        for (int q = 0; q < 4; ++q)
            LDSM_X4(b[2 * q][0], b[2 * q][1], b[2 * q + 1][0], b[2 * q + 1][1], baddr[q] + koff);
#pragma unroll
        for (int mt = 0; mt < 2; ++mt)
#pragma unroll
            for (int nt = 0; nt < 8; ++nt) {
                asm volatile(
                    "mma.sync.aligned.m16n8k16.row.col.f32.bf16.bf16.f32 "
                    "{%0,%1,%2,%3}, {%4,%5,%6,%7}, {%8,%9}, {%0,%1,%2,%3};"
                    : "+f"(acc[mt][nt][0]), "+f"(acc[mt][nt][1]),
                      "+f"(acc[mt][nt][2]), "+f"(acc[mt][nt][3])
                    : "r"(a[mt][0]), "r"(a[mt][1]), "r"(a[mt][2]), "r"(a[mt][3]),
                      "r"(b[nt][0]), "r"(b[nt][1]));
            }
    }
    // No barrier: partial arrays don't alias As/Bs.

    // ---- register-pooled epilogue ----
    int rids[4];
#pragma unroll
    for (int mt = 0; mt < 2; ++mt)
#pragma unroll
        for (int half = 0; half < 2; ++half)
            rids[mt * 2 + half] = s_idr[wm * 32 + mt * 16 + g + half * 8];

    float rmin[4] = {POS_INF_F, POS_INF_F, POS_INF_F, POS_INF_F};
    float rmax[4] = {NEG_INF_F, NEG_INF_F, NEG_INF_F, NEG_INF_F};

#pragma unroll
    for (int ph = 0; ph < 2; ++ph) {                 // two phases of 4 nt (8 cols)
        float cmin[8], cmax[8];
        int cids[8];
#pragma unroll
        for (int i = 0; i < 8; ++i) {
            cmin[i] = POS_INF_F; cmax[i] = NEG_INF_F;
            int nt = ph * 4 + (i >> 1);
            cids[i] = s_idc[wn * 64 + nt * 8 + 2 * tig + (i & 1)];
        }
#pragma unroll
        for (int i = 0; i < 8; ++i) {
            const int nt = ph * 4 + (i >> 1), e = i & 1;
            const int lc = wn * 64 + nt * 8 + 2 * tig + e;
            const int cid = cids[i];
#pragma unroll
            for (int mt = 0; mt < 2; ++mt)
#pragma unroll
                for (int half = 0; half < 2; ++half) {
                    const int ri = mt * 2 + half;
                    float s = acc[mt][nt][half * 2 + e];
                    if (diag && (wm * 32 + mt * 16 + g + half * 8) == lc) s = 0.0f;
                    if (rids[ri] == cid) {
                        rmin[ri] = fminf(rmin[ri], s);
                        cmin[i]  = fminf(cmin[i], s);
                    } else {
                        rmax[ri] = fmaxf(rmax[ri], s);
                        cmax[i]  = fmaxf(cmax[i], s);
                    }
                }
        }
        if (!diag) {
            const int slot = wm * 8 + g;             // 0..31
#pragma unroll
            for (int i = 0; i < 8; ++i) {
                const int nt = ph * 4 + (i >> 1);
                const int lc = wn * 64 + nt * 8 + 2 * tig + (i & 1);
                sCol[slot * BM + lc] = make_float2(cmin[i], cmax[i]);
            }
        }
    }
    {
        const int slot = wn * 4 + tig;               // 0..7
#pragma unroll
        for (int ri = 0; ri < 4; ++ri) {
            const int lr = wm * 32 + (ri >> 1) * 16 + g + (ri & 1) * 8;
            sRow[slot * BM + lr] = make_float2(rmin[ri], rmax[ri]);
        }
    }
    __syncthreads();

    if (tid < BM) {
        float vmin = POS_INF_F, vmax = NEG_INF_F;
#pragma unroll
        for (int s = 0; s < 8; ++s) {
            float2 p = sRow[s * BM + tid];
            vmin = fminf(vmin, p.x);
            vmax = fmaxf(vmax, p.y);
        }
        atomicMax(&g_max_enc[m0 + tid], enc_f(vmax));
        atomicMin(&g_min_enc[m0 + tid], enc_f(vmin));
    } else if (!diag) {
        const int c = tid - BM;
        float vmin = POS_INF_F, vmax = NEG_INF_F;
#pragma unroll
        for (int s = 0; s < 32; ++s) {
            float2 p = sCol[s * BM + c];
            vmin = fminf(vmin, p.x);
            vmax = fmaxf(vmax, p.y);
        }
        atomicMax(&g_max_enc[n0 + c], enc_f(vmax));
        atomicMin(&g_min_enc[n0 + c], enc_f(vmin));
    }
}

// ---------------------------------------------------------------------------
// Kernel 3: deterministic scalar reduction of the hinge loss.
// ---------------------------------------------------------------------------
__global__ void finalize_kernel(float* __restrict__ out) {
    __shared__ float part[1024];
    float s = 0.0f;
    for (int i = threadIdx.x; i < B_ROWS; i += 1024) {
        s += fmaxf(MARGIN_F + dec_f(g_max_enc[i]) - dec_f(g_min_enc[i]), 0.0f);
    }
    part[threadIdx.x] = s;
    __syncthreads();
    for (int o = 512; o; o >>= 1) {
        if (threadIdx.x < o) part[threadIdx.x] += part[threadIdx.x + o];
        __syncthreads();
    }
    if (threadIdx.x == 0) out[0] = part[0];
}

extern "C" void kernel_launch(void* const* d_in, const int* in_sizes, int n_in,
                              void* d_out, int out_size) {
    const float* im  = (const float*)d_in[0];
    const void*  ids = d_in[1];

    cudaFuncSetAttribute(tile_kernel, cudaFuncAttributeMaxDynamicSharedMemorySize, SMEM_TOTAL);

    convert_kernel<<<256, 256>>>(im, ids);
    tile_kernel<<<NTILES, 256, SMEM_TOTAL>>>();
    finalize_kernel<<<1, 1024>>>((float*)d_out);
}

// round 12
// speedup vs baseline: 1.0861x; 1.0430x over previous
#include <cuda_runtime.h>
#include <cuda_bf16.h>
#include <cstdint>

#define B_ROWS 8192
#define DIM    128
#define BM     128
#define SH     136            // halves per smem bf16 row (272 B): LDSM conflict-free
#define NTILES 2080           // 64*65/2 upper-triangle tiles (incl. diagonal)
#define NCTA   296            // persistent CTAs: 2 per SM on 148 SMs
#define NEG_INF_F (-1e30f)
#define POS_INF_F ( 1e30f)
#define MARGIN_F  0.2f

// smem layout (dynamic): A | B0 | B1 | sRow ; sCol aliases B[p]
#define AB_BYTES   (BM * SH * 2)                   // 34816
#define B_OFF(p)   (AB_BYTES + (p) * AB_BYTES)
#define SROW_OFF   (3 * AB_BYTES)                  // 104448
#define SMEM_TOTAL (SROW_OFF + 8 * BM * 8)         // 112640

// ---------------- device-global state ----------------
__device__ unsigned       g_max_enc[B_ROWS];
__device__ unsigned       g_min_enc[B_ROWS];
__device__ __nv_bfloat16  g_im_bf16[B_ROWS * DIM];   // 2 MB, L2-resident
__device__ int            g_ids32[B_ROWS];

__device__ __forceinline__ unsigned enc_f(float f) {
    unsigned u = __float_as_uint(f);
    return (u & 0x80000000u) ? ~u : (u | 0x80000000u);
}
__device__ __forceinline__ float dec_f(unsigned u) {
    return __uint_as_float((u & 0x80000000u) ? (u & 0x7FFFFFFFu) : ~u);
}
__device__ __forceinline__ uint32_t smem_u32(const void* p) {
    uint32_t a;
    asm("{ .reg .u64 t; cvta.to.shared.u64 t, %1; cvt.u32.u64 %0, t; }" : "=r"(a) : "l"(p));
    return a;
}
#define LDSM_X4(r0, r1, r2, r3, addr) \
    asm volatile("ldmatrix.sync.aligned.m8n8.x4.shared.b16 {%0,%1,%2,%3}, [%4];" \
                 : "=r"(r0), "=r"(r1), "=r"(r2), "=r"(r3) : "r"(addr))
#define CP_ASYNC16(dst, src) \
    asm volatile("cp.async.cg.shared.global [%0], [%1], 16;" :: "r"(dst), "l"(src))
#define CP_COMMIT() asm volatile("cp.async.commit_group;" ::: "memory")
#define CP_WAIT0()  asm volatile("cp.async.wait_group 0;" ::: "memory")

// ---------------------------------------------------------------------------
// Kernel 1: convert im -> bf16, ids -> int32, clear reductions (as R11).
// ---------------------------------------------------------------------------
__global__ void convert_kernel(const float* __restrict__ im, const void* __restrict__ ids) {
    __shared__ int s_is64;
    const int tid = blockIdx.x * blockDim.x + threadIdx.x;   // 65536

    if (blockIdx.x < 32) {
        if (threadIdx.x < 32) {
            const unsigned* w = (const unsigned*)ids;
            unsigned v = w[2 * threadIdx.x + 1] | w[2 * threadIdx.x + 65];
            unsigned any = __ballot_sync(0xffffffffu, v != 0u);
            if (threadIdx.x == 0) s_is64 = (any == 0u) ? 1 : 0;
        }
        __syncthreads();
        g_max_enc[tid] = enc_f(NEG_INF_F);
        g_min_enc[tid] = enc_f(POS_INF_F);
        g_ids32[tid] = s_is64 ? (int)((const long long*)ids)[tid]
                              : ((const int*)ids)[tid];
    }
    const float4* in4 = (const float4*)im;
    float4 v0 = in4[tid];
    float4 v1 = in4[tid + 65536];
    float4 v2 = in4[tid + 131072];
    float4 v3 = in4[tid + 196608];
    __nv_bfloat162* o = (__nv_bfloat162*)g_im_bf16;
    o[2 * tid + 0]            = __floats2bfloat162_rn(v0.x, v0.y);
    o[2 * tid + 1]            = __floats2bfloat162_rn(v0.z, v0.w);
    o[2 * (tid + 65536) + 0]  = __floats2bfloat162_rn(v1.x, v1.y);
    o[2 * (tid + 65536) + 1]  = __floats2bfloat162_rn(v1.z, v1.w);
    o[2 * (tid + 131072) + 0] = __floats2bfloat162_rn(v2.x, v2.y);
    o[2 * (tid + 131072) + 1] = __floats2bfloat162_rn(v2.z, v2.w);
    o[2 * (tid + 196608) + 0] = __floats2bfloat162_rn(v3.x, v3.y);
    o[2 * (tid + 196608) + 1] = __floats2bfloat162_rn(v3.z, v3.w);
}

// ---------------------------------------------------------------------------
// Kernel 2: persistent tiles, cp.async double-buffered B, A reuse per row-run.
// Tiles ordered lexicographically: row bi holds tiles (bi,bi)..(bi,63);
// S(b) = 64b - b(b-1)/2 is the first tile index of row b.
// ---------------------------------------------------------------------------
__global__ void __launch_bounds__(256, 2)
tile_kernel(void) {
    extern __shared__ char smem[];
    __shared__ int s_idr[BM], s_idc[BM];
    const int tid = threadIdx.x;
    const uint32_t smem_base = smem_u32(smem);

    const int t0 = (int)(((long long)blockIdx.x * NTILES) / NCTA);
    const int t1 = (int)(((long long)(blockIdx.x + 1) * NTILES) / NCTA);
    if (t0 >= t1) return;

    // coords of tile t0
    int bi = (int)((129.0f - sqrtf(16641.0f - 8.0f * (float)t0)) * 0.5f);
    if (bi < 0) bi = 0;
    if (bi > 63) bi = 63;
    while (bi > 0 && 64 * bi - bi * (bi - 1) / 2 > t0) --bi;
    while (64 * (bi + 1) - (bi + 1) * bi / 2 <= t0) ++bi;
    int bj = bi + (t0 - (64 * bi - bi * (bi - 1) / 2));

    // cp.async tile stage: 2048 16B chunks, 8 per thread
#define STAGE(dstoff, row0) do {                                              \
        uint32_t _d = smem_base + (dstoff);                                   \
        const char* _s = (const char*)(g_im_bf16 + (size_t)(row0) * DIM);     \
        _Pragma("unroll")                                                     \
        for (int _it = 0; _it < 8; ++_it) {                                   \
            int _idx = _it * 256 + tid;                                       \
            int _row = _idx >> 4, _q = _idx & 15;                             \
            CP_ASYNC16(_d + _row * (SH * 2) + _q * 16, _s + _row * 256 + _q * 16); \
        } } while (0)

    STAGE(0, bi * BM);          // A
    STAGE(B_OFF(0), bj * BM);   // B(t0)
    CP_COMMIT();

    const int warp = tid >> 5, lane = tid & 31;
    const int wm = warp >> 1, wn = warp & 1;
    const int g = lane >> 2, tig = lane & 3;
    const int grp = lane >> 3, rin = lane & 7;

    uint32_t aaddr[2];
#pragma unroll
    for (int mt = 0; mt < 2; ++mt)
        aaddr[mt] = smem_base + 2 * ((wm * 32 + mt * 16 + (grp & 1) * 8 + rin) * SH + (grp >> 1) * 8);

    int p = 0;
    for (int t = t0; t < t1; ++t, p ^= 1) {
        const int m0 = bi * BM, n0 = bj * BM;
        const bool diag = (bi == bj);
        int nbi = bi, nbj = bj + 1;
        if (nbj == 64) { ++nbi; nbj = nbi; }

        CP_WAIT0();                              // tile data landed
        if (tid < BM) {
            s_idr[tid] = g_ids32[m0 + tid];
            s_idc[tid] = g_ids32[n0 + tid];
        }
        __syncthreads();

        const uint32_t Bs32 = smem_base + B_OFF(p);
        uint32_t baddr[4];
#pragma unroll
        for (int q = 0; q < 4; ++q)
            baddr[q] = Bs32 + 2 * ((wn * 64 + 16 * q + (grp >> 1) * 8 + rin) * SH + (grp & 1) * 8);

        float acc[2][8][4];
#pragma unroll
        for (int mt = 0; mt < 2; ++mt)
#pragma unroll
            for (int nt = 0; nt < 8; ++nt)
#pragma unroll
                for (int r = 0; r < 4; ++r) acc[mt][nt][r] = 0.0f;

#pragma unroll
        for (int ks = 0; ks < 8; ++ks) {
            const uint32_t koff = ks * 32;
            unsigned a[2][4], b[8][2];
#pragma unroll
            for (int mt = 0; mt < 2; ++mt)
                LDSM_X4(a[mt][0], a[mt][1], a[mt][2], a[mt][3], aaddr[mt] + koff);
#pragma unroll
            for (int q = 0; q < 4; ++q)
                LDSM_X4(b[2 * q][0], b[2 * q][1], b[2 * q + 1][0], b[2 * q + 1][1], baddr[q] + koff);
#pragma unroll
            for (int mt = 0; mt < 2; ++mt)
#pragma unroll
                for (int nt = 0; nt < 8; ++nt) {
                    asm volatile(
                        "mma.sync.aligned.m16n8k16.row.col.f32.bf16.bf16.f32 "
                        "{%0,%1,%2,%3}, {%4,%5,%6,%7}, {%8,%9}, {%0,%1,%2,%3};"
                        : "+f"(acc[mt][nt][0]), "+f"(acc[mt][nt][1]),
                          "+f"(acc[mt][nt][2]), "+f"(acc[mt][nt][3])
                        : "r"(a[mt][0]), "r"(a[mt][1]), "r"(a[mt][2]), "r"(a[mt][3]),
                          "r"(b[nt][0]), "r"(b[nt][1]));
                }
        }
        __syncthreads();                         // done reading A and B[p]

        // prefetch next tile into B[1-p] (and A if the row changes)
        if (t + 1 < t1) {
            if (nbi != bi) STAGE(0, nbi * BM);
            STAGE(B_OFF(1 - p), nbj * BM);
            CP_COMMIT();
        }

        // ---- register-pooled epilogue (exact R9 math); sCol aliases B[p] ----
        float2* sRow = (float2*)(smem + SROW_OFF);
        float2* sCol = (float2*)(smem + B_OFF(p));

        int rids[4];
#pragma unroll
        for (int mt = 0; mt < 2; ++mt)
#pragma unroll
            for (int half = 0; half < 2; ++half)
                rids[mt * 2 + half] = s_idr[wm * 32 + mt * 16 + g + half * 8];

        float rmin[4] = {POS_INF_F, POS_INF_F, POS_INF_F, POS_INF_F};
        float rmax[4] = {NEG_INF_F, NEG_INF_F, NEG_INF_F, NEG_INF_F};

#pragma unroll
        for (int ph = 0; ph < 2; ++ph) {
            float cmin[8], cmax[8];
            int cids[8];
#pragma unroll
            for (int i = 0; i < 8; ++i) {
                cmin[i] = POS_INF_F; cmax[i] = NEG_INF_F;
                int nt = ph * 4 + (i >> 1);
                cids[i] = s_idc[wn * 64 + nt * 8 + 2 * tig + (i & 1)];
            }
#pragma unroll
            for (int i = 0; i < 8; ++i) {
                const int nt = ph * 4 + (i >> 1), e = i & 1;
                const int lc = wn * 64 + nt * 8 + 2 * tig + e;
                const int cid = cids[i];
#pragma unroll
                for (int mt = 0; mt < 2; ++mt)
#pragma unroll
                    for (int half = 0; half < 2; ++half) {
                        const int ri = mt * 2 + half;
                        float s = acc[mt][nt][half * 2 + e];
                        if (diag && (wm * 32 + mt * 16 + g + half * 8) == lc) s = 0.0f;
                        if (rids[ri] == cid) {
                            rmin[ri] = fminf(rmin[ri], s);
                            cmin[i]  = fminf(cmin[i], s);
                        } else {
                            rmax[ri] = fmaxf(rmax[ri], s);
                            cmax[i]  = fmaxf(cmax[i], s);
                        }
                    }
            }
            if (!diag) {
                const int slot = wm * 8 + g;
#pragma unroll
                for (int i = 0; i < 8; ++i) {
                    const int nt = ph * 4 + (i >> 1);
                    const int lc = wn * 64 + nt * 8 + 2 * tig + (i & 1);
                    sCol[slot * BM + lc] = make_float2(cmin[i], cmax[i]);
                }
            }
        }
        {
            const int slot = wn * 4 + tig;
#pragma unroll
            for (int ri = 0; ri < 4; ++ri) {
                const int lr = wm * 32 + (ri >> 1) * 16 + g + (ri & 1) * 8;
                sRow[slot * BM + lr] = make_float2(rmin[ri], rmax[ri]);
            }
        }
        __syncthreads();

        if (tid < BM) {
            float vmin = POS_INF_F, vmax = NEG_INF_F;
#pragma unroll
            for (int s = 0; s < 8; ++s) {
                float2 q = sRow[s * BM + tid];
                vmin = fminf(vmin, q.x);
                vmax = fmaxf(vmax, q.y);
            }
            atomicMax(&g_max_enc[m0 + tid], enc_f(vmax));
            atomicMin(&g_min_enc[m0 + tid], enc_f(vmin));
        } else if (!diag) {
            const int c = tid - BM;
            float vmin = POS_INF_F, vmax = NEG_INF_F;
#pragma unroll
            for (int s = 0; s < 32; ++s) {
                float2 q = sCol[s * BM + c];
                vmin = fminf(vmin, q.x);
                vmax = fmaxf(vmax, q.y);
            }
            atomicMax(&g_max_enc[n0 + c], enc_f(vmax));
            atomicMin(&g_min_enc[n0 + c], enc_f(vmin));
        }
        __syncthreads();                         // partials free; ids may be rewritten

        bi = nbi; bj = nbj;
    }
#undef STAGE
}

// ---------------------------------------------------------------------------
// Kernel 3: deterministic scalar reduction of the hinge loss.
// ---------------------------------------------------------------------------
__global__ void finalize_kernel(float* __restrict__ out) {
    __shared__ float part[1024];
    float s = 0.0f;
    for (int i = threadIdx.x; i < B_ROWS; i += 1024) {
        s += fmaxf(MARGIN_F + dec_f(g_max_enc[i]) - dec_f(g_min_enc[i]), 0.0f);
    }
    part[threadIdx.x] = s;
    __syncthreads();
    for (int o = 512; o; o >>= 1) {
        if (threadIdx.x < o) part[threadIdx.x] += part[threadIdx.x + o];
        __syncthreads();
    }
    if (threadIdx.x == 0) out[0] = part[0];
}

extern "C" void kernel_launch(void* const* d_in, const int* in_sizes, int n_in,
                              void* d_out, int out_size) {
    const float* im  = (const float*)d_in[0];
    const void*  ids = d_in[1];

    cudaFuncSetAttribute(tile_kernel, cudaFuncAttributeMaxDynamicSharedMemorySize, SMEM_TOTAL);

    convert_kernel<<<256, 256>>>(im, ids);
    tile_kernel<<<NCTA, 256, SMEM_TOTAL>>>();
    finalize_kernel<<<1, 1024>>>((float*)d_out);
}